// round 1
// baseline (speedup 1.0000x reference)
#include <cuda_runtime.h>
#include <math.h>

// Problem constants (match reference_code)
#define NN   100000
#define NE   1600000
#define FIN  128
#define HID  64
#define NG   256
#define PD_EPS 1e-6f

#define NB16   ((NN + 15) / 16)       // 6250 blocks, 16 nodes per 256-thread block
#define NB256  ((NN + 255) / 256)     // 391
#define EB256  ((NE + 255) / 256)     // 6250
#define SCAN_NB ((NN + 1023) / 1024)  // 98

// ---------------- scratch (static __device__, no allocation) ----------------
__device__ float g_buf0[NN * HID];
__device__ float g_buf1[NN * HID];
__device__ float g_dinv[NN];
__device__ int   g_deg[NN];
__device__ int   g_rowptr[NN + 1];
__device__ int   g_cursor[NN];
__device__ int   g_csrc[NE];
__device__ float g_cw[NE];
__device__ float g_pool[2 * NG * HID];
__device__ float g_cnt[2 * NG];
__device__ float g_emb[2 * NG * HID];
__device__ int   g_bsum[128];
__device__ int   g_boff[128];

// ---------------- degree / dinv ----------------
__global__ void k_deg_init() {
    int i = blockIdx.x * blockDim.x + threadIdx.x;
    if (i < NN) g_deg[i] = 1;   // self loop
}

__global__ void k_deg_count(const int* __restrict__ dst) {
    int e = blockIdx.x * blockDim.x + threadIdx.x;
    if (e < NE) atomicAdd(&g_deg[dst[e]], 1);
}

__global__ void k_dinv() {
    int i = blockIdx.x * blockDim.x + threadIdx.x;
    if (i < NN) g_dinv[i] = rsqrtf((float)g_deg[i]);
}

// ---------------- exclusive scan of (deg-1) -> rowptr ----------------
__global__ void k_scanA() {   // 1024 threads/block
    __shared__ int sh[1024];
    int i = blockIdx.x * 1024 + threadIdx.x;
    int v = (i < NN) ? (g_deg[i] - 1) : 0;
    int val = v;
    sh[threadIdx.x] = val;
    __syncthreads();
    for (int off = 1; off < 1024; off <<= 1) {
        int t = (threadIdx.x >= off) ? sh[threadIdx.x - off] : 0;
        __syncthreads();
        val += t;
        sh[threadIdx.x] = val;
        __syncthreads();
    }
    if (i < NN) g_rowptr[i] = val - v;          // exclusive within block
    if (threadIdx.x == 1023) g_bsum[blockIdx.x] = val;  // block total
}

__global__ void k_scanB() {
    if (threadIdx.x == 0 && blockIdx.x == 0) {
        int run = 0;
        for (int b = 0; b < SCAN_NB; b++) { g_boff[b] = run; run += g_bsum[b]; }
    }
}

__global__ void k_scanC() {
    int i = blockIdx.x * blockDim.x + threadIdx.x;
    if (i < NN) {
        int v = g_rowptr[i] + g_boff[i >> 10];
        g_rowptr[i] = v;
        g_cursor[i] = v;
    }
    if (i == 0) g_rowptr[NN] = NE;
}

// ---------------- CSR fill (by destination) ----------------
__global__ void k_fill(const int* __restrict__ src, const int* __restrict__ dst) {
    int e = blockIdx.x * blockDim.x + threadIdx.x;
    if (e >= NE) return;
    int s = src[e], d = dst[e];
    int p = atomicAdd(&g_cursor[d], 1);
    g_csrc[p] = s;
    g_cw[p] = g_dinv[s] * g_dinv[d];
}

// ---------------- GEMM: out[N,64] = X[N,K] @ W[K,64] ----------------
template <int K>
__global__ void k_gemm(const float* __restrict__ X, const float* __restrict__ W,
                       float* __restrict__ out) {
    __shared__ float sW[K * 64];
    for (int i = threadIdx.x; i < K * 64; i += blockDim.x) sW[i] = W[i];
    __syncthreads();

    int t = threadIdx.x;                  // 256 threads: 16 rows x 16 col-segments
    int row = blockIdx.x * 16 + (t >> 4);
    int cseg = (t & 15) * 4;
    if (row >= NN) return;

    float acc0 = 0.f, acc1 = 0.f, acc2 = 0.f, acc3 = 0.f;
    const float4* xr4 = (const float4*)(X + (size_t)row * K);
#pragma unroll 4
    for (int k4 = 0; k4 < K / 4; k4++) {
        float4 xq = xr4[k4];
        const float* wb = sW + (k4 * 4) * 64 + cseg;
        float4 w;
        w = *(const float4*)(wb + 0 * 64);
        acc0 += xq.x * w.x; acc1 += xq.x * w.y; acc2 += xq.x * w.z; acc3 += xq.x * w.w;
        w = *(const float4*)(wb + 1 * 64);
        acc0 += xq.y * w.x; acc1 += xq.y * w.y; acc2 += xq.y * w.z; acc3 += xq.y * w.w;
        w = *(const float4*)(wb + 2 * 64);
        acc0 += xq.z * w.x; acc1 += xq.z * w.y; acc2 += xq.z * w.z; acc3 += xq.z * w.w;
        w = *(const float4*)(wb + 3 * 64);
        acc0 += xq.w * w.x; acc1 += xq.w * w.y; acc2 += xq.w * w.z; acc3 += xq.w * w.w;
    }
    *(float4*)(out + (size_t)row * 64 + cseg) = make_float4(acc0, acc1, acc2, acc3);
}

// ---------------- aggregate: out[d] = dinv[d]^2*h[d] + sum_e w*h[src] + b (ReLU opt) ----
template <bool RELU>
__global__ void k_agg(const float* __restrict__ h, float* __restrict__ out,
                      const float* __restrict__ bias) {
    int t = threadIdx.x;
    int node = blockIdx.x * 16 + (t >> 4);
    int l4 = (t & 15) * 4;
    if (node >= NN) return;

    float di = g_dinv[node];
    float w0 = di * di;
    float4 hv = *(const float4*)(h + (size_t)node * 64 + l4);
    float a0 = w0 * hv.x, a1 = w0 * hv.y, a2 = w0 * hv.z, a3 = w0 * hv.w;

    int beg = g_rowptr[node], end = g_rowptr[node + 1];
#pragma unroll 2
    for (int e = beg; e < end; e++) {
        int s = g_csrc[e];
        float w = g_cw[e];
        float4 v = *(const float4*)(h + (size_t)s * 64 + l4);
        a0 += w * v.x; a1 += w * v.y; a2 += w * v.z; a3 += w * v.w;
    }
    float4 b4 = *(const float4*)(bias + l4);
    a0 += b4.x; a1 += b4.y; a2 += b4.z; a3 += b4.w;
    if (RELU) {
        a0 = fmaxf(a0, 0.f); a1 = fmaxf(a1, 0.f);
        a2 = fmaxf(a2, 0.f); a3 = fmaxf(a3, 0.f);
    }
    *(float4*)(out + (size_t)node * 64 + l4) = make_float4(a0, a1, a2, a3);
}

// ---------------- pooling ----------------
__global__ void k_zero_pools() {
    int i = blockIdx.x * blockDim.x + threadIdx.x;
    if (i < 2 * NG * HID) g_pool[i] = 0.f;
    if (i < 2 * NG) g_cnt[i] = 0.f;
}

__global__ void k_pool(const float* __restrict__ x, const int* __restrict__ batch,
                       float* __restrict__ pool, float* __restrict__ cnt) {
    int t = threadIdx.x;
    int node = blockIdx.x * 16 + (t >> 4);
    int l4 = (t & 15) * 4;
    if (node >= NN) return;
    int g = batch[node];
    float4 v = *(const float4*)(x + (size_t)node * 64 + l4);
    float* p = pool + g * HID + l4;
    atomicAdd(p + 0, v.x);
    atomicAdd(p + 1, v.y);
    atomicAdd(p + 2, v.z);
    atomicAdd(p + 3, v.w);
    if (l4 == 0) atomicAdd(&cnt[g], 1.0f);
}

__global__ void k_mlp(const float* __restrict__ Wlin, const float* __restrict__ blin,
                      const float* __restrict__ pool, const float* __restrict__ cnt,
                      float* __restrict__ emb) {
    int g = blockIdx.x;
    int c = threadIdx.x;   // 64 threads
    __shared__ float p[64];
    float cn = fmaxf(cnt[g], 1.0f);
    p[c] = pool[g * HID + c] / cn;
    __syncthreads();
    float acc = blin[c];
#pragma unroll 8
    for (int k = 0; k < 64; k++) acc += p[k] * Wlin[k * 64 + c];
    emb[g * HID + c] = acc;
}

__global__ void k_dist(float* __restrict__ out) {
    int g = blockIdx.x * blockDim.x + threadIdx.x;
    if (g >= NG) return;
    const float* e1 = g_emb + g * HID;
    const float* e2 = g_emb + NG * HID + g * HID;
    float s = 0.f;
#pragma unroll 8
    for (int c = 0; c < 64; c++) {
        float d = e1[c] - e2[c] + PD_EPS;
        s += d * d;
    }
    out[g] = sqrtf(s);
}

// ---------------- host orchestration ----------------
extern "C" void kernel_launch(void* const* d_in, const int* in_sizes, int n_in,
                              void* d_out, int out_size) {
    const float* x1  = (const float*)d_in[0];
    const int*   ei1 = (const int*)d_in[1];
    const int*   ba1 = (const int*)d_in[2];
    const float* x2  = (const float*)d_in[3];
    const int*   ei2 = (const int*)d_in[4];
    const int*   ba2 = (const int*)d_in[5];
    const float* W1  = (const float*)d_in[6];
    const float* b1  = (const float*)d_in[7];
    const float* W2  = (const float*)d_in[8];
    const float* b2  = (const float*)d_in[9];
    const float* W3  = (const float*)d_in[10];
    const float* b3  = (const float*)d_in[11];
    const float* Wl  = (const float*)d_in[12];
    const float* bl  = (const float*)d_in[13];
    float* out = (float*)d_out;

    void *pb0, *pb1, *ppool, *pcnt, *pemb;
    cudaGetSymbolAddress(&pb0, g_buf0);
    cudaGetSymbolAddress(&pb1, g_buf1);
    cudaGetSymbolAddress(&ppool, g_pool);
    cudaGetSymbolAddress(&pcnt, g_cnt);
    cudaGetSymbolAddress(&pemb, g_emb);
    float* buf0 = (float*)pb0;
    float* buf1 = (float*)pb1;
    float* pool = (float*)ppool;
    float* cnt  = (float*)pcnt;
    float* emb  = (float*)pemb;

    k_zero_pools<<<(2 * NG * HID + 255) / 256, 256>>>();

    for (int tw = 0; tw < 2; tw++) {
        const float* x   = tw ? x2 : x1;
        const int*   src = tw ? ei2 : ei1;
        const int*   dst = src + NE;
        const int*   bat = tw ? ba2 : ba1;

        // build degree / dinv / CSR (reused by all 3 layers)
        k_deg_init<<<NB256, 256>>>();
        k_deg_count<<<EB256, 256>>>(dst);
        k_dinv<<<NB256, 256>>>();
        k_scanA<<<SCAN_NB, 1024>>>();
        k_scanB<<<1, 32>>>();
        k_scanC<<<NB256, 256>>>();
        k_fill<<<EB256, 256>>>(src, dst);

        // layer 1
        k_gemm<FIN><<<NB16, 256>>>(x, W1, buf0);
        k_agg<true><<<NB16, 256>>>(buf0, buf1, b1);
        // layer 2
        k_gemm<HID><<<NB16, 256>>>(buf1, W2, buf0);
        k_agg<true><<<NB16, 256>>>(buf0, buf1, b2);
        // layer 3 (no relu)
        k_gemm<HID><<<NB16, 256>>>(buf1, W3, buf0);
        k_agg<false><<<NB16, 256>>>(buf0, buf1, b3);

        // mean pool + linear head
        k_pool<<<NB16, 256>>>(buf1, bat, pool + tw * NG * HID, cnt + tw * NG);
        k_mlp<<<NG, 64>>>(Wl, bl, pool + tw * NG * HID, cnt + tw * NG,
                          emb + tw * NG * HID);
    }

    k_dist<<<1, 256>>>(out);
}

// round 2
// speedup vs baseline: 1.3176x; 1.3176x over previous
#include <cuda_runtime.h>
#include <math.h>

// Problem constants
#define NN   100000
#define NE   1600000
#define NN2  (2 * NN)      // both towers concatenated
#define NE2  (2 * NE)
#define FIN  128
#define HID  64
#define NG   256
#define PD_EPS 1e-6f

#define SCAN_NB2 ((NN2 + 1023) / 1024)   // 196

// ---------------- scratch (static __device__, no allocation) ----------------
__device__ float g_buf0[NN2 * HID];
__device__ float g_buf1[NN2 * HID];
__device__ float g_dinv[NN2];
__device__ int   g_deg[NN2];
__device__ int   g_rowptr[NN2 + 1];
__device__ int   g_cursor[NN2];
__device__ int2  g_edge[NE2];           // {src_global, weight_bits}
__device__ float g_pool[2 * NG * HID];
__device__ float g_cnt[2 * NG];
__device__ float g_emb[2 * NG * HID];
__device__ int   g_bsum[256];
__device__ int   g_boff[256];

// ---------------- init: deg=1 (self loop), pools=0 ----------------
__global__ void k_init() {
    int i = blockIdx.x * blockDim.x + threadIdx.x;
    if (i < NN2) g_deg[i] = 1;
    if (i < 2 * NG * HID) g_pool[i] = 0.f;
    if (i < 2 * NG) g_cnt[i] = 0.f;
}

// ---------------- degree count over both towers ----------------
__global__ void k_deg_count(const int* __restrict__ dst1,
                            const int* __restrict__ dst2) {
    int e = blockIdx.x * blockDim.x + threadIdx.x;
    if (e >= NE2) return;
    int d = (e < NE) ? dst1[e] : (dst2[e - NE] + NN);
    atomicAdd(&g_deg[d], 1);
}

__global__ void k_dinv() {
    int i = blockIdx.x * blockDim.x + threadIdx.x;
    if (i < NN2) g_dinv[i] = rsqrtf((float)g_deg[i]);
}

// ---------------- exclusive scan of (deg-1) -> rowptr ----------------
__global__ void k_scanA() {   // 1024 threads/block
    __shared__ int sh[1024];
    int i = blockIdx.x * 1024 + threadIdx.x;
    int v = (i < NN2) ? (g_deg[i] - 1) : 0;
    int val = v;
    sh[threadIdx.x] = val;
    __syncthreads();
    for (int off = 1; off < 1024; off <<= 1) {
        int t = (threadIdx.x >= off) ? sh[threadIdx.x - off] : 0;
        __syncthreads();
        val += t;
        sh[threadIdx.x] = val;
        __syncthreads();
    }
    if (i < NN2) g_rowptr[i] = val - v;             // exclusive within block
    if (threadIdx.x == 1023) g_bsum[blockIdx.x] = val;
}

__global__ void k_scanB() {   // 256 threads, one block: scan block sums
    __shared__ int sh[256];
    int t = threadIdx.x;
    int v = (t < SCAN_NB2) ? g_bsum[t] : 0;
    int val = v;
    sh[t] = val;
    __syncthreads();
    for (int off = 1; off < 256; off <<= 1) {
        int u = (t >= off) ? sh[t - off] : 0;
        __syncthreads();
        val += u;
        sh[t] = val;
        __syncthreads();
    }
    g_boff[t] = val - v;   // exclusive
}

__global__ void k_scanC() {
    int i = blockIdx.x * blockDim.x + threadIdx.x;
    if (i < NN2) {
        int v = g_rowptr[i] + g_boff[i >> 10];
        g_rowptr[i] = v;
        g_cursor[i] = v;
    }
    if (i == 0) g_rowptr[NN2] = NE2;
}

// ---------------- CSR fill (by destination), weight fused ----------------
__global__ void k_fill(const int* __restrict__ src1, const int* __restrict__ dst1,
                       const int* __restrict__ src2, const int* __restrict__ dst2) {
    int e = blockIdx.x * blockDim.x + threadIdx.x;
    if (e >= NE2) return;
    int s, d;
    if (e < NE) { s = src1[e]; d = dst1[e]; }
    else        { s = src2[e - NE] + NN; d = dst2[e - NE] + NN; }
    int p = atomicAdd(&g_cursor[d], 1);
    float w = g_dinv[s] * g_dinv[d];
    g_edge[p] = make_int2(s, __float_as_int(w));
}

// ---------------- GEMM: out[n,64] = X[n,:K] @ W[K,64]; 4x4 register block ----
template <int K>
__global__ void k_gemm(const float* __restrict__ X1, const float* __restrict__ X2,
                       const float* __restrict__ W, float* __restrict__ out) {
    __shared__ float sW[K * 64];
    for (int i = threadIdx.x; i < K * 64; i += blockDim.x) sW[i] = W[i];
    __syncthreads();

    int t = threadIdx.x;              // 256 threads: 16 rowgroups x 16 colsegs
    int rg = t >> 4;                  // 0..15
    int cs = (t & 15) * 4;            // col base
    int row0 = blockIdx.x * 64 + rg * 4;

    const float4* xp[4];
#pragma unroll
    for (int r = 0; r < 4; r++) {
        int n = row0 + r;
        const float* base = (n < NN) ? (X1 + (size_t)n * K)
                                     : (X2 + (size_t)(n - NN) * K);
        xp[r] = (const float4*)base;
    }

    float acc[4][4];
#pragma unroll
    for (int r = 0; r < 4; r++)
#pragma unroll
        for (int c = 0; c < 4; c++) acc[r][c] = 0.f;

#pragma unroll 4
    for (int k4 = 0; k4 < K / 4; k4++) {
        float4 xq[4];
#pragma unroll
        for (int r = 0; r < 4; r++) xq[r] = xp[r][k4];
#pragma unroll
        for (int kk = 0; kk < 4; kk++) {
            float4 w = *(const float4*)(sW + (k4 * 4 + kk) * 64 + cs);
#pragma unroll
            for (int r = 0; r < 4; r++) {
                float xv = (kk == 0) ? xq[r].x : (kk == 1) ? xq[r].y
                         : (kk == 2) ? xq[r].z : xq[r].w;
                acc[r][0] += xv * w.x;
                acc[r][1] += xv * w.y;
                acc[r][2] += xv * w.z;
                acc[r][3] += xv * w.w;
            }
        }
    }
#pragma unroll
    for (int r = 0; r < 4; r++)
        *(float4*)(out + (size_t)(row0 + r) * 64 + cs) =
            make_float4(acc[r][0], acc[r][1], acc[r][2], acc[r][3]);
}

// ---------------- aggregate with unrolled-by-4 neighbor loop ----------------
template <bool RELU>
__global__ void k_agg(const float* __restrict__ h, float* __restrict__ out,
                      const float* __restrict__ bias) {
    int t = threadIdx.x;
    int node = blockIdx.x * 16 + (t >> 4);
    int lq = t & 15;                       // float4 lane within 64-float row
    if (node >= NN2) return;

    const float4* h4 = (const float4*)h;
    float di = g_dinv[node];
    float w0 = di * di;
    float4 hv = h4[(size_t)node * 16 + lq];
    float a0 = w0 * hv.x, a1 = w0 * hv.y, a2 = w0 * hv.z, a3 = w0 * hv.w;

    int e = g_rowptr[node];
    int end = g_rowptr[node + 1];
    int n = end - e;

    while (n >= 4) {
        int2 e0 = g_edge[e + 0];
        int2 e1 = g_edge[e + 1];
        int2 e2 = g_edge[e + 2];
        int2 e3 = g_edge[e + 3];
        float4 v0 = h4[(size_t)e0.x * 16 + lq];
        float4 v1 = h4[(size_t)e1.x * 16 + lq];
        float4 v2 = h4[(size_t)e2.x * 16 + lq];
        float4 v3 = h4[(size_t)e3.x * 16 + lq];
        float w_0 = __int_as_float(e0.y), w_1 = __int_as_float(e1.y);
        float w_2 = __int_as_float(e2.y), w_3 = __int_as_float(e3.y);
        a0 += w_0 * v0.x + w_1 * v1.x + w_2 * v2.x + w_3 * v3.x;
        a1 += w_0 * v0.y + w_1 * v1.y + w_2 * v2.y + w_3 * v3.y;
        a2 += w_0 * v0.z + w_1 * v1.z + w_2 * v2.z + w_3 * v3.z;
        a3 += w_0 * v0.w + w_1 * v1.w + w_2 * v2.w + w_3 * v3.w;
        e += 4; n -= 4;
    }
    while (n > 0) {
        int2 ed = g_edge[e];
        float4 v = h4[(size_t)ed.x * 16 + lq];
        float w = __int_as_float(ed.y);
        a0 += w * v.x; a1 += w * v.y; a2 += w * v.z; a3 += w * v.w;
        e++; n--;
    }

    float4 b4 = *(const float4*)(bias + lq * 4);
    a0 += b4.x; a1 += b4.y; a2 += b4.z; a3 += b4.w;
    if (RELU) {
        a0 = fmaxf(a0, 0.f); a1 = fmaxf(a1, 0.f);
        a2 = fmaxf(a2, 0.f); a3 = fmaxf(a3, 0.f);
    }
    *(float4*)(out + (size_t)node * 64 + lq * 4) = make_float4(a0, a1, a2, a3);
}

// ---------------- pooling ----------------
__global__ void k_pool(const float* __restrict__ x,
                       const int* __restrict__ ba1, const int* __restrict__ ba2) {
    int t = threadIdx.x;
    int node = blockIdx.x * 16 + (t >> 4);
    int l4 = (t & 15) * 4;
    if (node >= NN2) return;
    int g = (node < NN) ? ba1[node] : (NG + ba2[node - NN]);
    float4 v = *(const float4*)(x + (size_t)node * 64 + l4);
    float* p = g_pool + g * HID + l4;
    atomicAdd(p + 0, v.x);
    atomicAdd(p + 1, v.y);
    atomicAdd(p + 2, v.z);
    atomicAdd(p + 3, v.w);
    if (l4 == 0) atomicAdd(&g_cnt[g], 1.0f);
}

__global__ void k_mlp(const float* __restrict__ Wlin, const float* __restrict__ blin) {
    int g = blockIdx.x;        // 0..2NG-1
    int c = threadIdx.x;       // 64
    __shared__ float p[64];
    float cn = fmaxf(g_cnt[g], 1.0f);
    p[c] = g_pool[g * HID + c] / cn;
    __syncthreads();
    float acc = blin[c];
#pragma unroll 8
    for (int k = 0; k < 64; k++) acc += p[k] * Wlin[k * 64 + c];
    g_emb[g * HID + c] = acc;
}

__global__ void k_dist(float* __restrict__ out) {
    int g = blockIdx.x * blockDim.x + threadIdx.x;
    if (g >= NG) return;
    const float* e1 = g_emb + g * HID;
    const float* e2 = g_emb + (NG + g) * HID;
    float s = 0.f;
#pragma unroll 8
    for (int c = 0; c < 64; c++) {
        float d = e1[c] - e2[c] + PD_EPS;
        s += d * d;
    }
    out[g] = sqrtf(s);
}

// ---------------- host orchestration ----------------
extern "C" void kernel_launch(void* const* d_in, const int* in_sizes, int n_in,
                              void* d_out, int out_size) {
    const float* x1  = (const float*)d_in[0];
    const int*   ei1 = (const int*)d_in[1];
    const int*   ba1 = (const int*)d_in[2];
    const float* x2  = (const float*)d_in[3];
    const int*   ei2 = (const int*)d_in[4];
    const int*   ba2 = (const int*)d_in[5];
    const float* W1  = (const float*)d_in[6];
    const float* b1  = (const float*)d_in[7];
    const float* W2  = (const float*)d_in[8];
    const float* b2  = (const float*)d_in[9];
    const float* W3  = (const float*)d_in[10];
    const float* b3  = (const float*)d_in[11];
    const float* Wl  = (const float*)d_in[12];
    const float* bl  = (const float*)d_in[13];
    float* out = (float*)d_out;

    void *pb0, *pb1;
    cudaGetSymbolAddress(&pb0, g_buf0);
    cudaGetSymbolAddress(&pb1, g_buf1);
    float* buf0 = (float*)pb0;
    float* buf1 = (float*)pb1;

    const int* src1 = ei1;          const int* dst1 = ei1 + NE;
    const int* src2 = ei2;          const int* dst2 = ei2 + NE;

    int nbN  = (NN2 + 255) / 256;       // 782
    int nbE  = (NE2 + 255) / 256;       // 12500
    int nbG  = NN2 / 64;                // 3125 (NN2 % 64 == 0)
    int nbA  = (NN2 + 15) / 16;         // 12500

    // CSR build (shared by all 3 layers, both towers)
    k_init<<<nbN, 256>>>();
    k_deg_count<<<nbE, 256>>>(dst1, dst2);
    k_dinv<<<nbN, 256>>>();
    k_scanA<<<SCAN_NB2, 1024>>>();
    k_scanB<<<1, 256>>>();
    k_scanC<<<nbN, 256>>>();
    k_fill<<<nbE, 256>>>(src1, dst1, src2, dst2);

    // layer 1 (K=128)
    k_gemm<FIN><<<nbG, 256>>>(x1, x2, W1, buf0);
    k_agg<true><<<nbA, 256>>>(buf0, buf1, b1);
    // layer 2
    k_gemm<HID><<<nbG, 256>>>(buf1, buf1 + (size_t)NN * HID, W2, buf0);
    k_agg<true><<<nbA, 256>>>(buf0, buf1, b2);
    // layer 3 (no relu)
    k_gemm<HID><<<nbG, 256>>>(buf1, buf1 + (size_t)NN * HID, W3, buf0);
    k_agg<false><<<nbA, 256>>>(buf0, buf1, b3);

    // mean pool + linear head + distance
    k_pool<<<nbA, 256>>>(buf1, ba1, ba2);
    k_mlp<<<2 * NG, 64>>>(Wl, bl);
    k_dist<<<1, 256>>>(out);
}

// round 3
// speedup vs baseline: 1.5591x; 1.1833x over previous
#include <cuda_runtime.h>
#include <cuda_fp16.h>
#include <math.h>

// Problem constants
#define NN   100000
#define NE   1600000
#define NN2  (2 * NN)
#define NE2  (2 * NE)
#define FIN  128
#define HID  64
#define NG   256
#define PD_EPS 1e-6f

#define SCAN_NB2 ((NN2 + 1023) / 1024)   // 196

// ---------------- scratch ----------------
__device__ __half g_h0[NN2 * HID];      // GEMM output
__device__ __half g_h1[NN2 * HID];      // agg output
__device__ float g_dinv[NN2];
__device__ int   g_deg[NN2];
__device__ int   g_rowptr[NN2 + 1];
__device__ int   g_cursor[NN2];
__device__ int2  g_edge[NE2];           // {src_global, weight_bits(fp32)}
__device__ float g_pool[2 * NG * HID];
__device__ float g_cnt[2 * NG];
__device__ float g_emb[2 * NG * HID];
__device__ int   g_bsum[256];
__device__ int   g_boff[256];

__device__ __forceinline__ float4 h4_to_f4(uint2 u) {
    __half2 p0 = *(__half2*)&u.x;
    __half2 p1 = *(__half2*)&u.y;
    float2 f0 = __half22float2(p0);
    float2 f1 = __half22float2(p1);
    return make_float4(f0.x, f0.y, f1.x, f1.y);
}

__device__ __forceinline__ uint2 f4_to_h4(float a, float b, float c, float d) {
    uint2 u;
    __half2 p0 = __floats2half2_rn(a, b);
    __half2 p1 = __floats2half2_rn(c, d);
    u.x = *(unsigned*)&p0;
    u.y = *(unsigned*)&p1;
    return u;
}

// ---------------- init: deg=1 (self loop), pools=0 ----------------
__global__ void k_init() {
    int i = blockIdx.x * blockDim.x + threadIdx.x;
    if (i < NN2) g_deg[i] = 1;
    if (i < 2 * NG * HID) g_pool[i] = 0.f;
    if (i < 2 * NG) g_cnt[i] = 0.f;
}

__global__ void k_deg_count(const int* __restrict__ dst1,
                            const int* __restrict__ dst2) {
    int e = blockIdx.x * blockDim.x + threadIdx.x;
    if (e >= NE2) return;
    int d = (e < NE) ? dst1[e] : (dst2[e - NE] + NN);
    atomicAdd(&g_deg[d], 1);
}

// ---------------- scan of (deg-1) -> rowptr; also compute dinv ----------------
__global__ void k_scanA() {   // 1024 threads/block
    __shared__ int sh[1024];
    int i = blockIdx.x * 1024 + threadIdx.x;
    int deg = (i < NN2) ? g_deg[i] : 1;
    if (i < NN2) g_dinv[i] = rsqrtf((float)deg);
    int v = (i < NN2) ? (deg - 1) : 0;
    int val = v;
    sh[threadIdx.x] = val;
    __syncthreads();
    for (int off = 1; off < 1024; off <<= 1) {
        int t = (threadIdx.x >= off) ? sh[threadIdx.x - off] : 0;
        __syncthreads();
        val += t;
        sh[threadIdx.x] = val;
        __syncthreads();
    }
    if (i < NN2) g_rowptr[i] = val - v;
    if (threadIdx.x == 1023) g_bsum[blockIdx.x] = val;
}

__global__ void k_scanB() {
    __shared__ int sh[256];
    int t = threadIdx.x;
    int v = (t < SCAN_NB2) ? g_bsum[t] : 0;
    int val = v;
    sh[t] = val;
    __syncthreads();
    for (int off = 1; off < 256; off <<= 1) {
        int u = (t >= off) ? sh[t - off] : 0;
        __syncthreads();
        val += u;
        sh[t] = val;
        __syncthreads();
    }
    g_boff[t] = val - v;
}

__global__ void k_scanC() {
    int i = blockIdx.x * blockDim.x + threadIdx.x;
    if (i < NN2) {
        int v = g_rowptr[i] + g_boff[i >> 10];
        g_rowptr[i] = v;
        g_cursor[i] = v;
    }
    if (i == 0) g_rowptr[NN2] = NE2;
}

__global__ void k_fill(const int* __restrict__ src1, const int* __restrict__ dst1,
                       const int* __restrict__ src2, const int* __restrict__ dst2) {
    int e = blockIdx.x * blockDim.x + threadIdx.x;
    if (e >= NE2) return;
    int s, d;
    if (e < NE) { s = src1[e]; d = dst1[e]; }
    else        { s = src2[e - NE] + NN; d = dst2[e - NE] + NN; }
    int p = atomicAdd(&g_cursor[d], 1);
    float w = g_dinv[s] * g_dinv[d];
    g_edge[p] = make_int2(s, __float_as_int(w));
}

// ---------------- GEMM fp32 input (layer 1): out = X @ W, 8x4 reg block ----
template <int K>
__global__ void k_gemm_f32(const float* __restrict__ X1, const float* __restrict__ X2,
                           const float* __restrict__ W, __half* __restrict__ out) {
    __shared__ float sW[K * 64];
    for (int i = threadIdx.x; i < K * 64; i += blockDim.x) sW[i] = W[i];
    __syncthreads();

    int t = threadIdx.x;              // 256 = 16 rowgroups x 16 colsegs
    int rg = t >> 4;
    int cs = (t & 15) * 4;
    int row0 = blockIdx.x * 128 + rg * 8;

    const float4* xp[8];
#pragma unroll
    for (int r = 0; r < 8; r++) {
        int n = row0 + r;
        int nc = (n < NN2) ? n : (NN2 - 1);
        const float* base = (nc < NN) ? (X1 + (size_t)nc * K)
                                      : (X2 + (size_t)(nc - NN) * K);
        xp[r] = (const float4*)base;
    }

    float acc[8][4];
#pragma unroll
    for (int r = 0; r < 8; r++)
#pragma unroll
        for (int c = 0; c < 4; c++) acc[r][c] = 0.f;

    for (int k4 = 0; k4 < K / 4; k4++) {
        float4 xq[8];
#pragma unroll
        for (int r = 0; r < 8; r++) xq[r] = xp[r][k4];
#pragma unroll
        for (int kk = 0; kk < 4; kk++) {
            float4 w = *(const float4*)(sW + (k4 * 4 + kk) * 64 + cs);
#pragma unroll
            for (int r = 0; r < 8; r++) {
                float xv = (kk == 0) ? xq[r].x : (kk == 1) ? xq[r].y
                         : (kk == 2) ? xq[r].z : xq[r].w;
                acc[r][0] += xv * w.x;
                acc[r][1] += xv * w.y;
                acc[r][2] += xv * w.z;
                acc[r][3] += xv * w.w;
            }
        }
    }
#pragma unroll
    for (int r = 0; r < 8; r++) {
        int n = row0 + r;
        if (n < NN2)
            *(uint2*)(out + (size_t)n * 64 + cs) =
                f4_to_h4(acc[r][0], acc[r][1], acc[r][2], acc[r][3]);
    }
}

// ---------------- GEMM fp16 input (layers 2,3): K=64 ----------------
__global__ void k_gemm_f16(const __half* __restrict__ X, const float* __restrict__ W,
                           __half* __restrict__ out) {
    __shared__ float sW[64 * 64];
    for (int i = threadIdx.x; i < 64 * 64; i += blockDim.x) sW[i] = W[i];
    __syncthreads();

    int t = threadIdx.x;
    int rg = t >> 4;
    int cs = (t & 15) * 4;
    int row0 = blockIdx.x * 128 + rg * 8;

    const uint2* xp[8];   // 4 halves per uint2, 16 uint2 per row
#pragma unroll
    for (int r = 0; r < 8; r++) {
        int n = row0 + r;
        int nc = (n < NN2) ? n : (NN2 - 1);
        xp[r] = (const uint2*)(X + (size_t)nc * 64);
    }

    float acc[8][4];
#pragma unroll
    for (int r = 0; r < 8; r++)
#pragma unroll
        for (int c = 0; c < 4; c++) acc[r][c] = 0.f;

    for (int k4 = 0; k4 < 16; k4++) {
        float4 xq[8];
#pragma unroll
        for (int r = 0; r < 8; r++) xq[r] = h4_to_f4(xp[r][k4]);
#pragma unroll
        for (int kk = 0; kk < 4; kk++) {
            float4 w = *(const float4*)(sW + (k4 * 4 + kk) * 64 + cs);
#pragma unroll
            for (int r = 0; r < 8; r++) {
                float xv = (kk == 0) ? xq[r].x : (kk == 1) ? xq[r].y
                         : (kk == 2) ? xq[r].z : xq[r].w;
                acc[r][0] += xv * w.x;
                acc[r][1] += xv * w.y;
                acc[r][2] += xv * w.z;
                acc[r][3] += xv * w.w;
            }
        }
    }
#pragma unroll
    for (int r = 0; r < 8; r++) {
        int n = row0 + r;
        if (n < NN2)
            *(uint2*)(out + (size_t)n * 64 + cs) =
                f4_to_h4(acc[r][0], acc[r][1], acc[r][2], acc[r][3]);
    }
}

// ---------------- aggregate (fp16 rows, fp32 accumulate) ----------------
template <bool RELU>
__global__ void k_agg(const __half* __restrict__ h, __half* __restrict__ out,
                      const float* __restrict__ bias) {
    int t = threadIdx.x;
    int node = blockIdx.x * 16 + (t >> 4);
    int lq = t & 15;                       // 4-half lane within 64-half row
    if (node >= NN2) return;

    const uint2* h2 = (const uint2*)h;    // row stride = 16 uint2 (128B)
    float di = g_dinv[node];
    float w0 = di * di;
    float4 hv = h4_to_f4(h2[(size_t)node * 16 + lq]);
    float a0 = w0 * hv.x, a1 = w0 * hv.y, a2 = w0 * hv.z, a3 = w0 * hv.w;

    int e = g_rowptr[node];
    int end = g_rowptr[node + 1];
    int n = end - e;

    while (n >= 4) {
        int2 e0 = g_edge[e + 0];
        int2 e1 = g_edge[e + 1];
        int2 e2 = g_edge[e + 2];
        int2 e3 = g_edge[e + 3];
        float4 v0 = h4_to_f4(h2[(size_t)e0.x * 16 + lq]);
        float4 v1 = h4_to_f4(h2[(size_t)e1.x * 16 + lq]);
        float4 v2 = h4_to_f4(h2[(size_t)e2.x * 16 + lq]);
        float4 v3 = h4_to_f4(h2[(size_t)e3.x * 16 + lq]);
        float w_0 = __int_as_float(e0.y), w_1 = __int_as_float(e1.y);
        float w_2 = __int_as_float(e2.y), w_3 = __int_as_float(e3.y);
        a0 += w_0 * v0.x + w_1 * v1.x + w_2 * v2.x + w_3 * v3.x;
        a1 += w_0 * v0.y + w_1 * v1.y + w_2 * v2.y + w_3 * v3.y;
        a2 += w_0 * v0.z + w_1 * v1.z + w_2 * v2.z + w_3 * v3.z;
        a3 += w_0 * v0.w + w_1 * v1.w + w_2 * v2.w + w_3 * v3.w;
        e += 4; n -= 4;
    }
    while (n > 0) {
        int2 ed = g_edge[e];
        float4 v = h4_to_f4(h2[(size_t)ed.x * 16 + lq]);
        float w = __int_as_float(ed.y);
        a0 += w * v.x; a1 += w * v.y; a2 += w * v.z; a3 += w * v.w;
        e++; n--;
    }

    float4 b4 = *(const float4*)(bias + lq * 4);
    a0 += b4.x; a1 += b4.y; a2 += b4.z; a3 += b4.w;
    if (RELU) {
        a0 = fmaxf(a0, 0.f); a1 = fmaxf(a1, 0.f);
        a2 = fmaxf(a2, 0.f); a3 = fmaxf(a3, 0.f);
    }
    *(uint2*)(out + (size_t)node * 64 + lq * 4) = f4_to_h4(a0, a1, a2, a3);
}

// ---------------- pooling (fp16 in, fp32 atomics) ----------------
__global__ void k_pool(const __half* __restrict__ x,
                       const int* __restrict__ ba1, const int* __restrict__ ba2) {
    int t = threadIdx.x;
    int node = blockIdx.x * 16 + (t >> 4);
    int lq = t & 15;
    if (node >= NN2) return;
    int g = (node < NN) ? ba1[node] : (NG + ba2[node - NN]);
    float4 v = h4_to_f4(*(const uint2*)(x + (size_t)node * 64 + lq * 4));
    float* p = g_pool + g * HID + lq * 4;
    atomicAdd(p + 0, v.x);
    atomicAdd(p + 1, v.y);
    atomicAdd(p + 2, v.z);
    atomicAdd(p + 3, v.w);
    if (lq == 0) atomicAdd(&g_cnt[g], 1.0f);
}

__global__ void k_mlp(const float* __restrict__ Wlin, const float* __restrict__ blin) {
    int g = blockIdx.x;
    int c = threadIdx.x;
    __shared__ float p[64];
    float cn = fmaxf(g_cnt[g], 1.0f);
    p[c] = g_pool[g * HID + c] / cn;
    __syncthreads();
    float acc = blin[c];
#pragma unroll 8
    for (int k = 0; k < 64; k++) acc += p[k] * Wlin[k * 64 + c];
    g_emb[g * HID + c] = acc;
}

__global__ void k_dist(float* __restrict__ out) {
    int g = blockIdx.x * blockDim.x + threadIdx.x;
    if (g >= NG) return;
    const float* e1 = g_emb + g * HID;
    const float* e2 = g_emb + (NG + g) * HID;
    float s = 0.f;
#pragma unroll 8
    for (int c = 0; c < 64; c++) {
        float d = e1[c] - e2[c] + PD_EPS;
        s += d * d;
    }
    out[g] = sqrtf(s);
}

// ---------------- host orchestration ----------------
extern "C" void kernel_launch(void* const* d_in, const int* in_sizes, int n_in,
                              void* d_out, int out_size) {
    const float* x1  = (const float*)d_in[0];
    const int*   ei1 = (const int*)d_in[1];
    const int*   ba1 = (const int*)d_in[2];
    const float* x2  = (const float*)d_in[3];
    const int*   ei2 = (const int*)d_in[4];
    const int*   ba2 = (const int*)d_in[5];
    const float* W1  = (const float*)d_in[6];
    const float* b1  = (const float*)d_in[7];
    const float* W2  = (const float*)d_in[8];
    const float* b2  = (const float*)d_in[9];
    const float* W3  = (const float*)d_in[10];
    const float* b3  = (const float*)d_in[11];
    const float* Wl  = (const float*)d_in[12];
    const float* bl  = (const float*)d_in[13];
    float* out = (float*)d_out;

    void *ph0, *ph1;
    cudaGetSymbolAddress(&ph0, g_h0);
    cudaGetSymbolAddress(&ph1, g_h1);
    __half* h0 = (__half*)ph0;
    __half* h1 = (__half*)ph1;

    const int* src1 = ei1;          const int* dst1 = ei1 + NE;
    const int* src2 = ei2;          const int* dst2 = ei2 + NE;

    int nbN  = (NN2 + 255) / 256;       // 782
    int nbE  = (NE2 + 255) / 256;       // 12500
    int nbG  = (NN2 + 127) / 128;       // 1563
    int nbA  = (NN2 + 15) / 16;         // 12500

    // CSR build (shared by all 3 layers, both towers)
    k_init<<<nbN, 256>>>();
    k_deg_count<<<nbE, 256>>>(dst1, dst2);
    k_scanA<<<SCAN_NB2, 1024>>>();
    k_scanB<<<1, 256>>>();
    k_scanC<<<nbN, 256>>>();
    k_fill<<<nbE, 256>>>(src1, dst1, src2, dst2);

    // layer 1 (K=128, fp32 input)
    k_gemm_f32<FIN><<<nbG, 256>>>(x1, x2, W1, h0);
    k_agg<true><<<nbA, 256>>>(h0, h1, b1);
    // layer 2
    k_gemm_f16<<<nbG, 256>>>(h1, W2, h0);
    k_agg<true><<<nbA, 256>>>(h0, h1, b2);
    // layer 3 (no relu)
    k_gemm_f16<<<nbG, 256>>>(h1, W3, h0);
    k_agg<false><<<nbA, 256>>>(h0, h1, b3);

    // mean pool + linear head + distance
    k_pool<<<nbA, 256>>>(h1, ba1, ba2);
    k_mlp<<<2 * NG, 64>>>(Wl, bl);
    k_dist<<<1, 256>>>(out);
}

// round 4
// speedup vs baseline: 1.6316x; 1.0465x over previous
#include <cuda_runtime.h>
#include <cuda_fp16.h>
#include <mma.h>
#include <math.h>

using namespace nvcuda;

// Problem constants
#define NN   100000
#define NE   1600000
#define NN2  (2 * NN)
#define NE2  (2 * NE)
#define FIN  128
#define HID  64
#define NG   256
#define PD_EPS 1e-6f

#define SCAN_NB2 ((NN2 + 1023) / 1024)   // 196

// ---------------- scratch ----------------
__device__ __half g_x16[NN2 * FIN];     // fp16 copy of input features
__device__ __half g_h0[NN2 * HID];      // GEMM output
__device__ __half g_h1[NN2 * HID];      // agg output
__device__ __half g_wh[FIN * HID + 2 * HID * HID];  // fp16 weights
__device__ float g_dinv[NN2];
__device__ int   g_deg[NN2];
__device__ int   g_rowptr[NN2 + 1];
__device__ int   g_cursor[NN2];
__device__ int2  g_edge[NE2];           // {src_global, weight_bits(fp32)}
__device__ float g_pool[2 * NG * HID];
__device__ float g_cnt[2 * NG];
__device__ float g_emb[2 * NG * HID];
__device__ int   g_bsum[256];
__device__ int   g_boff[256];

__device__ __forceinline__ float4 h4_to_f4(uint2 u) {
    __half2 p0 = *(__half2*)&u.x;
    __half2 p1 = *(__half2*)&u.y;
    float2 f0 = __half22float2(p0);
    float2 f1 = __half22float2(p1);
    return make_float4(f0.x, f0.y, f1.x, f1.y);
}

__device__ __forceinline__ uint2 f4_to_h4(float a, float b, float c, float d) {
    uint2 u;
    __half2 p0 = __floats2half2_rn(a, b);
    __half2 p1 = __floats2half2_rn(c, d);
    u.x = *(unsigned*)&p0;
    u.y = *(unsigned*)&p1;
    return u;
}

// ---------------- init ----------------
__global__ void k_init() {
    int i = blockIdx.x * blockDim.x + threadIdx.x;
    if (i < NN2) g_deg[i] = 1;
    if (i < 2 * NG * HID) g_pool[i] = 0.f;
    if (i < 2 * NG) g_cnt[i] = 0.f;
}

__global__ void k_deg_count(const int* __restrict__ dst1,
                            const int* __restrict__ dst2) {
    int e = blockIdx.x * blockDim.x + threadIdx.x;
    if (e >= NE2) return;
    int d = (e < NE) ? dst1[e] : (dst2[e - NE] + NN);
    atomicAdd(&g_deg[d], 1);
}

__global__ void k_scanA() {
    __shared__ int sh[1024];
    int i = blockIdx.x * 1024 + threadIdx.x;
    int deg = (i < NN2) ? g_deg[i] : 1;
    if (i < NN2) g_dinv[i] = rsqrtf((float)deg);
    int v = (i < NN2) ? (deg - 1) : 0;
    int val = v;
    sh[threadIdx.x] = val;
    __syncthreads();
    for (int off = 1; off < 1024; off <<= 1) {
        int t = (threadIdx.x >= off) ? sh[threadIdx.x - off] : 0;
        __syncthreads();
        val += t;
        sh[threadIdx.x] = val;
        __syncthreads();
    }
    if (i < NN2) g_rowptr[i] = val - v;
    if (threadIdx.x == 1023) g_bsum[blockIdx.x] = val;
}

__global__ void k_scanB() {
    __shared__ int sh[256];
    int t = threadIdx.x;
    int v = (t < SCAN_NB2) ? g_bsum[t] : 0;
    int val = v;
    sh[t] = val;
    __syncthreads();
    for (int off = 1; off < 256; off <<= 1) {
        int u = (t >= off) ? sh[t - off] : 0;
        __syncthreads();
        val += u;
        sh[t] = val;
        __syncthreads();
    }
    g_boff[t] = val - v;
}

__global__ void k_scanC() {
    int i = blockIdx.x * blockDim.x + threadIdx.x;
    if (i < NN2) {
        int v = g_rowptr[i] + g_boff[i >> 10];
        g_rowptr[i] = v;
        g_cursor[i] = v;
    }
    if (i == 0) g_rowptr[NN2] = NE2;
}

__global__ void k_fill(const int* __restrict__ src1, const int* __restrict__ dst1,
                       const int* __restrict__ src2, const int* __restrict__ dst2) {
    int e = blockIdx.x * blockDim.x + threadIdx.x;
    if (e >= NE2) return;
    int s, d;
    if (e < NE) { s = src1[e]; d = dst1[e]; }
    else        { s = src2[e - NE] + NN; d = dst2[e - NE] + NN; }
    int p = atomicAdd(&g_cursor[d], 1);
    float w = g_dinv[s] * g_dinv[d];
    g_edge[p] = make_int2(s, __float_as_int(w));
}

// ---------------- converts ----------------
__global__ void k_cvt_x(const float* __restrict__ x1, const float* __restrict__ x2) {
    int i = blockIdx.x * blockDim.x + threadIdx.x;   // index of float4 group
    const int TOT = NN2 * FIN / 4;                   // 6.4M
    if (i >= TOT) return;
    const int HALF = NN * FIN / 4;
    float4 v = (i < HALF) ? ((const float4*)x1)[i] : ((const float4*)x2)[i - HALF];
    ((uint2*)g_x16)[i] = f4_to_h4(v.x, v.y, v.z, v.w);
}

__global__ void k_cvt_w(const float* __restrict__ W1, const float* __restrict__ W2,
                        const float* __restrict__ W3) {
    int i = blockIdx.x * blockDim.x + threadIdx.x;
    const int N1 = FIN * HID, N2 = HID * HID;
    if (i < N1) g_wh[i] = __float2half_rn(W1[i]);
    else if (i < N1 + N2) g_wh[i] = __float2half_rn(W2[i - N1]);
    else if (i < N1 + 2 * N2) g_wh[i] = __float2half_rn(W3[i - N1 - N2]);
}

// ---------------- tensor-core GEMM: out[NN2,64] = X[NN2,K] @ W[K,64] ----------
template <int K>
__global__ void k_gemm_tc(const __half* __restrict__ X, const __half* __restrict__ Wh,
                          __half* __restrict__ out) {
    __shared__ __half sW[K * 64];
    __shared__ float sOut[8][16 * 64];       // 8 warps x 4KB
    int tid = threadIdx.x;                   // 256 threads = 8 warps
    for (int i = tid; i < K * 64 / 8; i += 256)
        ((uint4*)sW)[i] = ((const uint4*)Wh)[i];
    __syncthreads();

    int warp = tid >> 5;
    int lane = tid & 31;
    int row0 = blockIdx.x * 128 + warp * 16;
    if (row0 >= NN2) return;                 // NN2 % 16 == 0, whole-tile guard

    wmma::fragment<wmma::accumulator, 16, 16, 16, float> acc[4];
#pragma unroll
    for (int n = 0; n < 4; n++) wmma::fill_fragment(acc[n], 0.f);

#pragma unroll
    for (int k = 0; k < K; k += 16) {
        wmma::fragment<wmma::matrix_a, 16, 16, 16, __half, wmma::row_major> a;
        wmma::load_matrix_sync(a, X + (size_t)row0 * K + k, K);
#pragma unroll
        for (int n = 0; n < 4; n++) {
            wmma::fragment<wmma::matrix_b, 16, 16, 16, __half, wmma::row_major> b;
            wmma::load_matrix_sync(b, sW + k * 64 + n * 16, 64);
            wmma::mma_sync(acc[n], a, b, acc[n]);
        }
    }
#pragma unroll
    for (int n = 0; n < 4; n++)
        wmma::store_matrix_sync(&sOut[warp][n * 16], acc[n], 64, wmma::mem_row_major);
    __syncwarp();

    const float* so = sOut[warp];
#pragma unroll
    for (int i = lane; i < 16 * 64 / 4; i += 32) {
        float4 v = ((const float4*)so)[i];
        int r = i >> 4, c4 = i & 15;
        *(uint2*)(out + (size_t)(row0 + r) * 64 + c4 * 4) =
            f4_to_h4(v.x, v.y, v.z, v.w);
    }
}

// ---------------- aggregate (fp16 rows, fp32 accumulate) ----------------
template <bool RELU>
__global__ void k_agg(const __half* __restrict__ h, __half* __restrict__ out,
                      const float* __restrict__ bias) {
    int t = threadIdx.x;
    int node = blockIdx.x * 16 + (t >> 4);
    int lq = t & 15;
    if (node >= NN2) return;

    const uint2* h2 = (const uint2*)h;
    float di = g_dinv[node];
    float w0 = di * di;
    float4 hv = h4_to_f4(h2[(size_t)node * 16 + lq]);
    float a0 = w0 * hv.x, a1 = w0 * hv.y, a2 = w0 * hv.z, a3 = w0 * hv.w;

    int e = g_rowptr[node];
    int end = g_rowptr[node + 1];
    int n = end - e;

    while (n >= 4) {
        int2 e0 = g_edge[e + 0];
        int2 e1 = g_edge[e + 1];
        int2 e2 = g_edge[e + 2];
        int2 e3 = g_edge[e + 3];
        float4 v0 = h4_to_f4(h2[(size_t)e0.x * 16 + lq]);
        float4 v1 = h4_to_f4(h2[(size_t)e1.x * 16 + lq]);
        float4 v2 = h4_to_f4(h2[(size_t)e2.x * 16 + lq]);
        float4 v3 = h4_to_f4(h2[(size_t)e3.x * 16 + lq]);
        float w_0 = __int_as_float(e0.y), w_1 = __int_as_float(e1.y);
        float w_2 = __int_as_float(e2.y), w_3 = __int_as_float(e3.y);
        a0 += w_0 * v0.x + w_1 * v1.x + w_2 * v2.x + w_3 * v3.x;
        a1 += w_0 * v0.y + w_1 * v1.y + w_2 * v2.y + w_3 * v3.y;
        a2 += w_0 * v0.z + w_1 * v1.z + w_2 * v2.z + w_3 * v3.z;
        a3 += w_0 * v0.w + w_1 * v1.w + w_2 * v2.w + w_3 * v3.w;
        e += 4; n -= 4;
    }
    while (n > 0) {
        int2 ed = g_edge[e];
        float4 v = h4_to_f4(h2[(size_t)ed.x * 16 + lq]);
        float w = __int_as_float(ed.y);
        a0 += w * v.x; a1 += w * v.y; a2 += w * v.z; a3 += w * v.w;
        e++; n--;
    }

    float4 b4 = *(const float4*)(bias + lq * 4);
    a0 += b4.x; a1 += b4.y; a2 += b4.z; a3 += b4.w;
    if (RELU) {
        a0 = fmaxf(a0, 0.f); a1 = fmaxf(a1, 0.f);
        a2 = fmaxf(a2, 0.f); a3 = fmaxf(a3, 0.f);
    }
    *(uint2*)(out + (size_t)node * 64 + lq * 4) = f4_to_h4(a0, a1, a2, a3);
}

// ---------------- pooling ----------------
__global__ void k_pool(const __half* __restrict__ x,
                       const int* __restrict__ ba1, const int* __restrict__ ba2) {
    int t = threadIdx.x;
    int node = blockIdx.x * 16 + (t >> 4);
    int lq = t & 15;
    if (node >= NN2) return;
    int g = (node < NN) ? ba1[node] : (NG + ba2[node - NN]);
    float4 v = h4_to_f4(*(const uint2*)(x + (size_t)node * 64 + lq * 4));
    float* p = g_pool + g * HID + lq * 4;
    atomicAdd(p + 0, v.x);
    atomicAdd(p + 1, v.y);
    atomicAdd(p + 2, v.z);
    atomicAdd(p + 3, v.w);
    if (lq == 0) atomicAdd(&g_cnt[g], 1.0f);
}

__global__ void k_mlp(const float* __restrict__ Wlin, const float* __restrict__ blin) {
    int g = blockIdx.x;
    int c = threadIdx.x;
    __shared__ float p[64];
    float cn = fmaxf(g_cnt[g], 1.0f);
    p[c] = g_pool[g * HID + c] / cn;
    __syncthreads();
    float acc = blin[c];
#pragma unroll 8
    for (int k = 0; k < 64; k++) acc += p[k] * Wlin[k * 64 + c];
    g_emb[g * HID + c] = acc;
}

__global__ void k_dist(float* __restrict__ out) {
    int g = blockIdx.x * blockDim.x + threadIdx.x;
    if (g >= NG) return;
    const float* e1 = g_emb + g * HID;
    const float* e2 = g_emb + (NG + g) * HID;
    float s = 0.f;
#pragma unroll 8
    for (int c = 0; c < 64; c++) {
        float d = e1[c] - e2[c] + PD_EPS;
        s += d * d;
    }
    out[g] = sqrtf(s);
}

// ---------------- host orchestration ----------------
extern "C" void kernel_launch(void* const* d_in, const int* in_sizes, int n_in,
                              void* d_out, int out_size) {
    const float* x1  = (const float*)d_in[0];
    const int*   ei1 = (const int*)d_in[1];
    const int*   ba1 = (const int*)d_in[2];
    const float* x2  = (const float*)d_in[3];
    const int*   ei2 = (const int*)d_in[4];
    const int*   ba2 = (const int*)d_in[5];
    const float* W1  = (const float*)d_in[6];
    const float* b1  = (const float*)d_in[7];
    const float* W2  = (const float*)d_in[8];
    const float* b2  = (const float*)d_in[9];
    const float* W3  = (const float*)d_in[10];
    const float* b3  = (const float*)d_in[11];
    const float* Wl  = (const float*)d_in[12];
    const float* bl  = (const float*)d_in[13];
    float* out = (float*)d_out;

    void *px, *ph0, *ph1, *pw;
    cudaGetSymbolAddress(&px, g_x16);
    cudaGetSymbolAddress(&ph0, g_h0);
    cudaGetSymbolAddress(&ph1, g_h1);
    cudaGetSymbolAddress(&pw, g_wh);
    __half* x16 = (__half*)px;
    __half* h0 = (__half*)ph0;
    __half* h1 = (__half*)ph1;
    __half* wh = (__half*)pw;

    const int* src1 = ei1;          const int* dst1 = ei1 + NE;
    const int* src2 = ei2;          const int* dst2 = ei2 + NE;

    int nbN  = (NN2 + 255) / 256;        // 782
    int nbE  = (NE2 + 255) / 256;        // 12500
    int nbG  = (NN2 + 127) / 128;        // 1563
    int nbA  = (NN2 + 15) / 16;          // 12500
    int nbCX = (NN2 * FIN / 4 + 255) / 256;  // 25000
    int nbCW = (FIN * HID + 2 * HID * HID + 255) / 256;

    // CSR build (shared by all 3 layers, both towers)
    k_init<<<nbN, 256>>>();
    k_deg_count<<<nbE, 256>>>(dst1, dst2);
    k_scanA<<<SCAN_NB2, 1024>>>();
    k_scanB<<<1, 256>>>();
    k_scanC<<<nbN, 256>>>();
    k_fill<<<nbE, 256>>>(src1, dst1, src2, dst2);

    // fp16 conversions
    k_cvt_w<<<nbCW, 256>>>(W1, W2, W3);
    k_cvt_x<<<nbCX, 256>>>(x1, x2);

    // layer 1 (K=128)
    k_gemm_tc<FIN><<<nbG, 256>>>(x16, wh, h0);
    k_agg<true><<<nbA, 256>>>(h0, h1, b1);
    // layer 2
    k_gemm_tc<HID><<<nbG, 256>>>(h1, wh + FIN * HID, h0);
    k_agg<true><<<nbA, 256>>>(h0, h1, b2);
    // layer 3 (no relu)
    k_gemm_tc<HID><<<nbG, 256>>>(h1, wh + FIN * HID + HID * HID, h0);
    k_agg<false><<<nbA, 256>>>(h0, h1, b3);

    // mean pool + linear head + distance
    k_pool<<<nbA, 256>>>(h1, ba1, ba2);
    k_mlp<<<2 * NG, 64>>>(Wl, bl);
    k_dist<<<1, 256>>>(out);
}

// round 5
// speedup vs baseline: 1.7250x; 1.0572x over previous
#include <cuda_runtime.h>
#include <cuda_fp16.h>
#include <mma.h>
#include <math.h>

using namespace nvcuda;

#define NN   100000
#define NE   1600000
#define NN2  (2 * NN)
#define NE2  (2 * NE)
#define FIN  128
#define HID  64
#define NG   256
#define PD_EPS 1e-6f

#define SCAN_NB2 ((NN2 + 1023) / 1024)   // 196

// ---------------- scratch ----------------
__device__ __half g_x16[NN2 * FIN];
__device__ __half g_h0[NN2 * HID];
__device__ __half g_h1[NN2 * HID];
__device__ __half g_wh[FIN * HID + 2 * HID * HID];
__device__ float g_dinv[NN2];
__device__ int   g_deg[NN2];
__device__ int   g_rowptr[NN2 + 1];
__device__ int   g_cursor[NN2];
__device__ int2  g_edge[NE2];
__device__ float g_pool[2 * NG * HID];
__device__ float g_cnt[2 * NG];
__device__ int   g_bsum[256];

__device__ __forceinline__ float4 h4_to_f4(uint2 u) {
    __half2 p0 = *(__half2*)&u.x;
    __half2 p1 = *(__half2*)&u.y;
    float2 f0 = __half22float2(p0);
    float2 f1 = __half22float2(p1);
    return make_float4(f0.x, f0.y, f1.x, f1.y);
}

__device__ __forceinline__ uint2 f4_to_h4(float a, float b, float c, float d) {
    uint2 u;
    __half2 p0 = __floats2half2_rn(a, b);
    __half2 p1 = __floats2half2_rn(c, d);
    u.x = *(unsigned*)&p0;
    u.y = *(unsigned*)&p1;
    return u;
}

// ---------------- setup kernels ----------------
__global__ void k_init() {
    int i = blockIdx.x * blockDim.x + threadIdx.x;
    if (i < NN2) g_deg[i] = 1;
    if (i < 2 * NG * HID) g_pool[i] = 0.f;
    if (i < 2 * NG) g_cnt[i] = 0.f;
}

__global__ void k_deg_count(const int* __restrict__ dst1,
                            const int* __restrict__ dst2) {
    int e = blockIdx.x * blockDim.x + threadIdx.x;
    if (e >= NE2) return;
    int d = (e < NE) ? dst1[e] : (dst2[e - NE] + NN);
    atomicAdd(&g_deg[d], 1);
}

__global__ void k_scanA() {     // 1024 threads x 196 blocks
    __shared__ int sh[1024];
    int i = blockIdx.x * 1024 + threadIdx.x;
    int deg = (i < NN2) ? g_deg[i] : 1;
    if (i < NN2) g_dinv[i] = rsqrtf((float)deg);
    int v = (i < NN2) ? (deg - 1) : 0;
    int val = v;
    sh[threadIdx.x] = val;
    __syncthreads();
    for (int off = 1; off < 1024; off <<= 1) {
        int t = (threadIdx.x >= off) ? sh[threadIdx.x - off] : 0;
        __syncthreads();
        val += t;
        sh[threadIdx.x] = val;
        __syncthreads();
    }
    if (i < NN2) g_rowptr[i] = val - v;
    if (threadIdx.x == 1023) g_bsum[blockIdx.x] = val;
}

// merged scanB+scanC: each block re-scans the 196 block sums locally
__global__ void k_scanC() {     // 1024 threads x 196 blocks
    __shared__ int sb[256];
    int t = threadIdx.x;
    int val = 0;
    if (t < 256) {
        val = (t < SCAN_NB2) ? g_bsum[t] : 0;
        sb[t] = val;
    }
    __syncthreads();
    for (int off = 1; off < 256; off <<= 1) {
        int u = (t < 256 && t >= off) ? sb[t - off] : 0;
        __syncthreads();
        if (t < 256) { val += u; sb[t] = val; }
        __syncthreads();
    }
    int offset = (blockIdx.x == 0) ? 0 : sb[blockIdx.x - 1];
    int i = blockIdx.x * 1024 + t;
    if (i < NN2) {
        int v = g_rowptr[i] + offset;
        g_rowptr[i] = v;
        g_cursor[i] = v;
    }
    if (i == 0) g_rowptr[NN2] = NE2;
}

__global__ void k_fill(const int* __restrict__ src1, const int* __restrict__ dst1,
                       const int* __restrict__ src2, const int* __restrict__ dst2) {
    int e = blockIdx.x * blockDim.x + threadIdx.x;
    if (e >= NE2) return;
    int s, d;
    if (e < NE) { s = src1[e]; d = dst1[e]; }
    else        { s = src2[e - NE] + NN; d = dst2[e - NE] + NN; }
    int p = atomicAdd(&g_cursor[d], 1);
    float w = g_dinv[s] * g_dinv[d];
    g_edge[p] = make_int2(s, __float_as_int(w));
}

// ---------------- converts ----------------
__global__ void k_cvt_x(const float* __restrict__ x1, const float* __restrict__ x2) {
    int i = blockIdx.x * blockDim.x + threadIdx.x;
    const int TOT = NN2 * FIN / 4;
    if (i >= TOT) return;
    const int HALF = NN * FIN / 4;
    float4 v = (i < HALF) ? ((const float4*)x1)[i] : ((const float4*)x2)[i - HALF];
    ((uint2*)g_x16)[i] = f4_to_h4(v.x, v.y, v.z, v.w);
}

__global__ void k_cvt_w(const float* __restrict__ W1, const float* __restrict__ W2,
                        const float* __restrict__ W3) {
    int i = blockIdx.x * blockDim.x + threadIdx.x;
    const int N1 = FIN * HID, N2 = HID * HID;
    if (i < N1) g_wh[i] = __float2half_rn(W1[i]);
    else if (i < N1 + N2) g_wh[i] = __float2half_rn(W2[i - N1]);
    else if (i < N1 + 2 * N2) g_wh[i] = __float2half_rn(W3[i - N1 - N2]);
}

// ---------------- layer-1 tensor-core GEMM ----------------
template <int K>
__global__ void k_gemm_tc(const __half* __restrict__ X, const __half* __restrict__ Wh,
                          __half* __restrict__ out) {
    __shared__ __half sW[K * 64];
    __shared__ float sOut[8][16 * 64];
    int tid = threadIdx.x;
    for (int i = tid; i < K * 64 / 8; i += 256)
        ((uint4*)sW)[i] = ((const uint4*)Wh)[i];
    __syncthreads();

    int warp = tid >> 5;
    int lane = tid & 31;
    int row0 = blockIdx.x * 128 + warp * 16;
    if (row0 >= NN2) return;

    wmma::fragment<wmma::accumulator, 16, 16, 16, float> acc[4];
#pragma unroll
    for (int n = 0; n < 4; n++) wmma::fill_fragment(acc[n], 0.f);

#pragma unroll
    for (int k = 0; k < K; k += 16) {
        wmma::fragment<wmma::matrix_a, 16, 16, 16, __half, wmma::row_major> a;
        wmma::load_matrix_sync(a, X + (size_t)row0 * K + k, K);
#pragma unroll
        for (int n = 0; n < 4; n++) {
            wmma::fragment<wmma::matrix_b, 16, 16, 16, __half, wmma::row_major> b;
            wmma::load_matrix_sync(b, sW + k * 64 + n * 16, 64);
            wmma::mma_sync(acc[n], a, b, acc[n]);
        }
    }
#pragma unroll
    for (int n = 0; n < 4; n++)
        wmma::store_matrix_sync(&sOut[warp][n * 16], acc[n], 64, wmma::mem_row_major);
    __syncwarp();

    const float* so = sOut[warp];
#pragma unroll
    for (int i = lane; i < 16 * 64 / 4; i += 32) {
        float4 v = ((const float4*)so)[i];
        int r = i >> 4, c4 = i & 15;
        *(uint2*)(out + (size_t)(row0 + r) * 64 + c4 * 4) =
            f4_to_h4(v.x, v.y, v.z, v.w);
    }
}

// ---------------- agg inner helper (8-way unrolled gathers) ----------------
__device__ __forceinline__ void agg_node(const uint2* __restrict__ h2, int node, int lq,
                                         float& a0, float& a1, float& a2, float& a3) {
    float di = g_dinv[node];
    float w0 = di * di;
    float4 hv = h4_to_f4(h2[(size_t)node * 16 + lq]);
    a0 = w0 * hv.x; a1 = w0 * hv.y; a2 = w0 * hv.z; a3 = w0 * hv.w;

    int e = g_rowptr[node];
    int n = g_rowptr[node + 1] - e;

    while (n >= 8) {
        int2 ed[8];
#pragma unroll
        for (int j = 0; j < 8; j++) ed[j] = g_edge[e + j];
        uint2 raw[8];
#pragma unroll
        for (int j = 0; j < 8; j++) raw[j] = h2[(size_t)ed[j].x * 16 + lq];
#pragma unroll
        for (int j = 0; j < 8; j++) {
            float w = __int_as_float(ed[j].y);
            float4 v = h4_to_f4(raw[j]);
            a0 += w * v.x; a1 += w * v.y; a2 += w * v.z; a3 += w * v.w;
        }
        e += 8; n -= 8;
    }
    while (n >= 4) {
        int2 ed[4];
#pragma unroll
        for (int j = 0; j < 4; j++) ed[j] = g_edge[e + j];
        uint2 raw[4];
#pragma unroll
        for (int j = 0; j < 4; j++) raw[j] = h2[(size_t)ed[j].x * 16 + lq];
#pragma unroll
        for (int j = 0; j < 4; j++) {
            float w = __int_as_float(ed[j].y);
            float4 v = h4_to_f4(raw[j]);
            a0 += w * v.x; a1 += w * v.y; a2 += w * v.z; a3 += w * v.w;
        }
        e += 4; n -= 4;
    }
    while (n > 0) {
        int2 ed = g_edge[e];
        float4 v = h4_to_f4(h2[(size_t)ed.x * 16 + lq]);
        float w = __int_as_float(ed.y);
        a0 += w * v.x; a1 += w * v.y; a2 += w * v.z; a3 += w * v.w;
        e++; n--;
    }
}

// ---------------- fused: a = relu(agg(h)+b); out = a @ W ----------------
__global__ __launch_bounds__(512)
void k_fused(const __half* __restrict__ h, const __half* __restrict__ Wh,
             const float* __restrict__ bias, __half* __restrict__ out) {
    __shared__ __half sW[64 * 64];
    __shared__ __half sA[32 * 64];
    __shared__ float sOut[8][16 * 16];
    int t = threadIdx.x;                   // 512 threads, 32 nodes/block

    for (int i = t; i < 64 * 64 / 8; i += 512)
        ((uint4*)sW)[i] = ((const uint4*)Wh)[i];

    int nl = t >> 4;                       // local node 0..31
    int lq = t & 15;
    int node = blockIdx.x * 32 + nl;       // NN2 % 32 == 0

    float a0, a1, a2, a3;
    agg_node((const uint2*)h, node, lq, a0, a1, a2, a3);
    float4 b4 = *(const float4*)(bias + lq * 4);
    a0 = fmaxf(a0 + b4.x, 0.f);
    a1 = fmaxf(a1 + b4.y, 0.f);
    a2 = fmaxf(a2 + b4.z, 0.f);
    a3 = fmaxf(a3 + b4.w, 0.f);
    *(uint2*)(sA + nl * 64 + lq * 4) = f4_to_h4(a0, a1, a2, a3);
    __syncthreads();

    if (t < 256) {
        int w = t >> 5;                    // 8 warps
        int lane = t & 31;
        int rt = w >> 2, nt = w & 3;       // row tile (2) x col tile (4)

        wmma::fragment<wmma::accumulator, 16, 16, 16, float> acc;
        wmma::fill_fragment(acc, 0.f);
#pragma unroll
        for (int k = 0; k < 4; k++) {
            wmma::fragment<wmma::matrix_a, 16, 16, 16, __half, wmma::row_major> a;
            wmma::fragment<wmma::matrix_b, 16, 16, 16, __half, wmma::row_major> b;
            wmma::load_matrix_sync(a, sA + rt * 16 * 64 + k * 16, 64);
            wmma::load_matrix_sync(b, sW + k * 16 * 64 + nt * 16, 64);
            wmma::mma_sync(acc, a, b, acc);
        }
        wmma::store_matrix_sync(sOut[w], acc, 16, wmma::mem_row_major);
        __syncwarp();

        int row0 = blockIdx.x * 32 + rt * 16;
#pragma unroll
        for (int i = lane; i < 64; i += 32) {     // 16 rows x 4 uint2-groups
            int r = i >> 2, c4 = i & 3;
            const float* p = sOut[w] + r * 16 + c4 * 4;
            *(uint2*)(out + (size_t)(row0 + r) * 64 + nt * 16 + c4 * 4) =
                f4_to_h4(p[0], p[1], p[2], p[3]);
        }
    }
}

// ---------------- fused: a = agg(h)+b; pool atomics ----------------
__global__ __launch_bounds__(512)
void k_fused_pool(const __half* __restrict__ h, const float* __restrict__ bias,
                  const int* __restrict__ ba1, const int* __restrict__ ba2) {
    int t = threadIdx.x;
    int node = blockIdx.x * 32 + (t >> 4);
    int lq = t & 15;

    float a0, a1, a2, a3;
    agg_node((const uint2*)h, node, lq, a0, a1, a2, a3);
    float4 b4 = *(const float4*)(bias + lq * 4);
    a0 += b4.x; a1 += b4.y; a2 += b4.z; a3 += b4.w;

    int g = (node < NN) ? ba1[node] : (NG + ba2[node - NN]);
    float* p = g_pool + g * HID + lq * 4;
    atomicAdd(p + 0, a0);
    atomicAdd(p + 1, a1);
    atomicAdd(p + 2, a2);
    atomicAdd(p + 3, a3);
    if (lq == 0) atomicAdd(&g_cnt[g], 1.0f);
}

// ---------------- fused mlp + distance ----------------
__global__ void k_mlp_dist(const float* __restrict__ Wlin, const float* __restrict__ blin,
                           float* __restrict__ out) {
    int g = blockIdx.x;       // 256
    int c = threadIdx.x;      // 64
    __shared__ float p1[64], p2[64], red[64];
    float cn1 = fmaxf(g_cnt[g], 1.0f);
    float cn2 = fmaxf(g_cnt[g + NG], 1.0f);
    p1[c] = g_pool[g * HID + c] / cn1;
    p2[c] = g_pool[(g + NG) * HID + c] / cn2;
    __syncthreads();
    float bv = blin[c];
    float e1 = bv, e2 = bv;
#pragma unroll 8
    for (int k = 0; k < 64; k++) {
        float w = Wlin[k * 64 + c];
        e1 += p1[k] * w;
        e2 += p2[k] * w;
    }
    float d = e1 - e2 + PD_EPS;
    red[c] = d * d;
    __syncthreads();
    if (c < 32) {
        float v = red[c] + red[c + 32];
#pragma unroll
        for (int off = 16; off > 0; off >>= 1)
            v += __shfl_down_sync(0xffffffff, v, off);
        if (c == 0) out[g] = sqrtf(v);
    }
}

// ---------------- host orchestration ----------------
extern "C" void kernel_launch(void* const* d_in, const int* in_sizes, int n_in,
                              void* d_out, int out_size) {
    const float* x1  = (const float*)d_in[0];
    const int*   ei1 = (const int*)d_in[1];
    const int*   ba1 = (const int*)d_in[2];
    const float* x2  = (const float*)d_in[3];
    const int*   ei2 = (const int*)d_in[4];
    const int*   ba2 = (const int*)d_in[5];
    const float* W1  = (const float*)d_in[6];
    const float* b1  = (const float*)d_in[7];
    const float* W2  = (const float*)d_in[8];
    const float* b2  = (const float*)d_in[9];
    const float* W3  = (const float*)d_in[10];
    const float* b3  = (const float*)d_in[11];
    const float* Wl  = (const float*)d_in[12];
    const float* bl  = (const float*)d_in[13];
    float* out = (float*)d_out;

    void *px, *ph0, *ph1, *pw;
    cudaGetSymbolAddress(&px, g_x16);
    cudaGetSymbolAddress(&ph0, g_h0);
    cudaGetSymbolAddress(&ph1, g_h1);
    cudaGetSymbolAddress(&pw, g_wh);
    __half* x16 = (__half*)px;
    __half* h0 = (__half*)ph0;
    __half* h1 = (__half*)ph1;
    __half* wh = (__half*)pw;

    const int* src1 = ei1;          const int* dst1 = ei1 + NE;
    const int* src2 = ei2;          const int* dst2 = ei2 + NE;

    int nbN  = (NN2 + 255) / 256;
    int nbE  = (NE2 + 255) / 256;
    int nbG  = (NN2 + 127) / 128;
    int nbF  = NN2 / 32;                       // 6250
    int nbCX = (NN2 * FIN / 4 + 255) / 256;
    int nbCW = (FIN * HID + 2 * HID * HID + 255) / 256;

    // order chosen so the profiler's captured launch (#3) is the hot GEMM
    k_cvt_w<<<nbCW, 256>>>(W1, W2, W3);                 // 0
    k_cvt_x<<<nbCX, 256>>>(x1, x2);                     // 1
    k_init<<<nbN, 256>>>();                             // 2
    k_gemm_tc<FIN><<<nbG, 256>>>(x16, wh, h0);          // 3  (hot)
    k_deg_count<<<nbE, 256>>>(dst1, dst2);              // 4
    k_scanA<<<SCAN_NB2, 1024>>>();                      // 5
    k_scanC<<<SCAN_NB2, 1024>>>();                      // 6
    k_fill<<<nbE, 256>>>(src1, dst1, src2, dst2);       // 7

    // fused layers
    k_fused<<<nbF, 512>>>(h0, wh + FIN * HID, b1, h1);                    // agg1+relu -> @W2
    k_fused<<<nbF, 512>>>(h1, wh + FIN * HID + HID * HID, b2, h0);        // agg2+relu -> @W3
    k_fused_pool<<<nbF, 512>>>(h0, b3, ba1, ba2);                         // agg3 + pool
    k_mlp_dist<<<NG, 64>>>(Wl, bl, out);
}

// round 6
// speedup vs baseline: 2.1600x; 1.2522x over previous
#include <cuda_runtime.h>
#include <cuda_fp16.h>
#include <mma.h>
#include <math.h>

using namespace nvcuda;

#define NN   100000
#define NE   1600000
#define NN2  (2 * NN)
#define NE2  (2 * NE)
#define FIN  128
#define HID  64
#define NG   256
#define PD_EPS 1e-6f

#define SCAN_NB2 ((NN2 + 1023) / 1024)   // 196
#define LDW 72                            // padded smem leading dim (halves)

// ---------------- scratch ----------------
__device__ __half g_x16[NN2 * FIN];
__device__ __half g_h0[NN2 * HID];
__device__ __half g_h1[NN2 * HID];
__device__ __half g_wh[FIN * HID + 2 * HID * HID];
__device__ float g_dinv[NN2];
__device__ int   g_deg[NN2];
__device__ int   g_rowptr[NN2 + 1];
__device__ int   g_cursor[NN2];
__device__ int2  g_edge[NE2];
__device__ float g_pool[2 * NG * HID];
__device__ float g_cnt[2 * NG];
__device__ int   g_bsum[256];

__device__ __forceinline__ float4 h4_to_f4(uint2 u) {
    __half2 p0 = *(__half2*)&u.x;
    __half2 p1 = *(__half2*)&u.y;
    float2 f0 = __half22float2(p0);
    float2 f1 = __half22float2(p1);
    return make_float4(f0.x, f0.y, f1.x, f1.y);
}

__device__ __forceinline__ uint2 f4_to_h4(float a, float b, float c, float d) {
    uint2 u;
    __half2 p0 = __floats2half2_rn(a, b);
    __half2 p1 = __floats2half2_rn(c, d);
    u.x = *(unsigned*)&p0;
    u.y = *(unsigned*)&p1;
    return u;
}

// ---------------- setup kernels ----------------
__global__ void k_init() {
    int i = blockIdx.x * blockDim.x + threadIdx.x;
    if (i < NN2) g_deg[i] = 1;
    if (i < 2 * NG * HID) g_pool[i] = 0.f;
    if (i < 2 * NG) g_cnt[i] = 0.f;
}

__global__ void k_deg_count(const int* __restrict__ dst1,
                            const int* __restrict__ dst2) {
    int e = blockIdx.x * blockDim.x + threadIdx.x;
    if (e >= NE2) return;
    int d = (e < NE) ? dst1[e] : (dst2[e - NE] + NN);
    atomicAdd(&g_deg[d], 1);
}

__global__ void k_scanA() {     // 1024 threads x 196 blocks
    __shared__ int sh[1024];
    int i = blockIdx.x * 1024 + threadIdx.x;
    int deg = (i < NN2) ? g_deg[i] : 1;
    if (i < NN2) g_dinv[i] = rsqrtf((float)deg);
    int v = (i < NN2) ? (deg - 1) : 0;
    int val = v;
    sh[threadIdx.x] = val;
    __syncthreads();
    for (int off = 1; off < 1024; off <<= 1) {
        int t = (threadIdx.x >= off) ? sh[threadIdx.x - off] : 0;
        __syncthreads();
        val += t;
        sh[threadIdx.x] = val;
        __syncthreads();
    }
    if (i < NN2) g_rowptr[i] = val - v;
    if (threadIdx.x == 1023) g_bsum[blockIdx.x] = val;
}

__global__ void k_scanC() {     // merged scanB+scanC
    __shared__ int sb[256];
    int t = threadIdx.x;
    int val = 0;
    if (t < 256) {
        val = (t < SCAN_NB2) ? g_bsum[t] : 0;
        sb[t] = val;
    }
    __syncthreads();
    for (int off = 1; off < 256; off <<= 1) {
        int u = (t < 256 && t >= off) ? sb[t - off] : 0;
        __syncthreads();
        if (t < 256) { val += u; sb[t] = val; }
        __syncthreads();
    }
    int offset = (blockIdx.x == 0) ? 0 : sb[blockIdx.x - 1];
    int i = blockIdx.x * 1024 + t;
    if (i < NN2) {
        int v = g_rowptr[i] + offset;
        g_rowptr[i] = v;
        g_cursor[i] = v;
    }
    if (i == 0) g_rowptr[NN2] = NE2;
}

__global__ void k_fill(const int* __restrict__ src1, const int* __restrict__ dst1,
                       const int* __restrict__ src2, const int* __restrict__ dst2) {
    int e = blockIdx.x * blockDim.x + threadIdx.x;
    if (e >= NE2) return;
    int s, d;
    if (e < NE) { s = src1[e]; d = dst1[e]; }
    else        { s = src2[e - NE] + NN; d = dst2[e - NE] + NN; }
    int p = atomicAdd(&g_cursor[d], 1);
    float w = g_dinv[s] * g_dinv[d];
    g_edge[p] = make_int2(s, __float_as_int(w));
}

// ---------------- converts ----------------
__global__ void k_cvt_x(const float* __restrict__ x1, const float* __restrict__ x2) {
    int i = blockIdx.x * blockDim.x + threadIdx.x;
    const int TOT = NN2 * FIN / 4;
    if (i >= TOT) return;
    const int HALF = NN * FIN / 4;
    float4 v = (i < HALF) ? ((const float4*)x1)[i] : ((const float4*)x2)[i - HALF];
    ((uint2*)g_x16)[i] = f4_to_h4(v.x, v.y, v.z, v.w);
}

__global__ void k_cvt_w(const float* __restrict__ W1, const float* __restrict__ W2,
                        const float* __restrict__ W3) {
    int i = blockIdx.x * blockDim.x + threadIdx.x;
    const int N1 = FIN * HID, N2 = HID * HID;
    if (i < N1) g_wh[i] = __float2half_rn(W1[i]);
    else if (i < N1 + N2) g_wh[i] = __float2half_rn(W2[i - N1]);
    else if (i < N1 + 2 * N2) g_wh[i] = __float2half_rn(W3[i - N1 - N2]);
}

// ---------------- layer-1 tensor-core GEMM: 256 rows/block, 32 rows/warp ----
template <int K>
__global__ __launch_bounds__(256)
void k_gemm_tc(const __half* __restrict__ X, const __half* __restrict__ Wh,
               __half* __restrict__ out) {
    __shared__ __half sW[K * LDW];            // padded, conflict-free frag loads
    __shared__ float sOut[8][16 * 16];
    int tid = threadIdx.x;
    // stage W: 8 halves per uint4, 8 groups per 64-wide row
    for (int i = tid; i < K * 8; i += 256) {
        int r = i >> 3, c = (i & 7) * 8;
        *(uint4*)(sW + r * LDW + c) = ((const uint4*)Wh)[i];
    }
    __syncthreads();

    int warp = tid >> 5;
    int lane = tid & 31;
    int row0 = blockIdx.x * 256 + warp * 32;
    if (row0 >= NN2) return;                  // NN2 % 32 == 0 per-warp guard

    wmma::fragment<wmma::accumulator, 16, 16, 16, float> acc[2][4];
#pragma unroll
    for (int r = 0; r < 2; r++)
#pragma unroll
        for (int n = 0; n < 4; n++) wmma::fill_fragment(acc[r][n], 0.f);

#pragma unroll
    for (int k = 0; k < K; k += 16) {
        wmma::fragment<wmma::matrix_a, 16, 16, 16, __half, wmma::row_major> a0, a1;
        wmma::load_matrix_sync(a0, X + (size_t)row0 * K + k, K);
        wmma::load_matrix_sync(a1, X + (size_t)(row0 + 16) * K + k, K);
#pragma unroll
        for (int n = 0; n < 4; n++) {
            wmma::fragment<wmma::matrix_b, 16, 16, 16, __half, wmma::row_major> b;
            wmma::load_matrix_sync(b, sW + k * LDW + n * 16, LDW);
            wmma::mma_sync(acc[0][n], a0, b, acc[0][n]);
            wmma::mma_sync(acc[1][n], a1, b, acc[1][n]);
        }
    }

    // epilogue: one 16x16 tile at a time through 1KB/warp smem
#pragma unroll
    for (int r = 0; r < 2; r++) {
#pragma unroll
        for (int n = 0; n < 4; n++) {
            wmma::store_matrix_sync(sOut[warp], acc[r][n], 16, wmma::mem_row_major);
            __syncwarp();
#pragma unroll
            for (int i = lane; i < 64; i += 32) {   // 16 rows x 4 float4 groups
                int rr = i >> 2, c4 = i & 3;
                const float* p = sOut[warp] + rr * 16 + c4 * 4;
                *(uint2*)(out + (size_t)(row0 + r * 16 + rr) * 64 + n * 16 + c4 * 4) =
                    f4_to_h4(p[0], p[1], p[2], p[3]);
            }
            __syncwarp();
        }
    }
}

// ---------------- agg inner helper (8-way unrolled gathers) ----------------
__device__ __forceinline__ void agg_node(const uint2* __restrict__ h2, int node, int lq,
                                         float& a0, float& a1, float& a2, float& a3) {
    float di = g_dinv[node];
    float w0 = di * di;
    float4 hv = h4_to_f4(h2[(size_t)node * 16 + lq]);
    a0 = w0 * hv.x; a1 = w0 * hv.y; a2 = w0 * hv.z; a3 = w0 * hv.w;

    int e = g_rowptr[node];
    int n = g_rowptr[node + 1] - e;

    while (n >= 8) {
        int2 ed[8];
#pragma unroll
        for (int j = 0; j < 8; j++) ed[j] = g_edge[e + j];
        uint2 raw[8];
#pragma unroll
        for (int j = 0; j < 8; j++) raw[j] = h2[(size_t)ed[j].x * 16 + lq];
#pragma unroll
        for (int j = 0; j < 8; j++) {
            float w = __int_as_float(ed[j].y);
            float4 v = h4_to_f4(raw[j]);
            a0 += w * v.x; a1 += w * v.y; a2 += w * v.z; a3 += w * v.w;
        }
        e += 8; n -= 8;
    }
    while (n >= 4) {
        int2 ed[4];
#pragma unroll
        for (int j = 0; j < 4; j++) ed[j] = g_edge[e + j];
        uint2 raw[4];
#pragma unroll
        for (int j = 0; j < 4; j++) raw[j] = h2[(size_t)ed[j].x * 16 + lq];
#pragma unroll
        for (int j = 0; j < 4; j++) {
            float w = __int_as_float(ed[j].y);
            float4 v = h4_to_f4(raw[j]);
            a0 += w * v.x; a1 += w * v.y; a2 += w * v.z; a3 += w * v.w;
        }
        e += 4; n -= 4;
    }
    while (n > 0) {
        int2 ed = g_edge[e];
        float4 v = h4_to_f4(h2[(size_t)ed.x * 16 + lq]);
        float w = __int_as_float(ed.y);
        a0 += w * v.x; a1 += w * v.y; a2 += w * v.z; a3 += w * v.w;
        e++; n--;
    }
}

// ---------------- fused: a = relu(agg(h)+b); out = a @ W ----------------
__global__ __launch_bounds__(512)
void k_fused(const __half* __restrict__ h, const __half* __restrict__ Wh,
             const float* __restrict__ bias, __half* __restrict__ out) {
    __shared__ __half sW[64 * LDW];
    __shared__ __half sA[32 * LDW];
    __shared__ float sOut[8][16 * 16];
    int t = threadIdx.x;                   // 512 threads, 32 nodes/block

    for (int i = t; i < 64 * 8; i += 512) {
        int r = i >> 3, c = (i & 7) * 8;
        *(uint4*)(sW + r * LDW + c) = ((const uint4*)Wh)[i];
    }

    int nl = t >> 4;                       // local node 0..31
    int lq = t & 15;
    int node = blockIdx.x * 32 + nl;       // NN2 % 32 == 0

    float a0, a1, a2, a3;
    agg_node((const uint2*)h, node, lq, a0, a1, a2, a3);
    float4 b4 = *(const float4*)(bias + lq * 4);
    a0 = fmaxf(a0 + b4.x, 0.f);
    a1 = fmaxf(a1 + b4.y, 0.f);
    a2 = fmaxf(a2 + b4.z, 0.f);
    a3 = fmaxf(a3 + b4.w, 0.f);
    *(uint2*)(sA + nl * LDW + lq * 4) = f4_to_h4(a0, a1, a2, a3);
    __syncthreads();

    if (t < 256) {
        int w = t >> 5;                    // 8 warps
        int lane = t & 31;
        int rt = w >> 2, nt = w & 3;       // row tile (2) x col tile (4)

        wmma::fragment<wmma::accumulator, 16, 16, 16, float> acc;
        wmma::fill_fragment(acc, 0.f);
#pragma unroll
        for (int k = 0; k < 4; k++) {
            wmma::fragment<wmma::matrix_a, 16, 16, 16, __half, wmma::row_major> a;
            wmma::fragment<wmma::matrix_b, 16, 16, 16, __half, wmma::row_major> b;
            wmma::load_matrix_sync(a, sA + rt * 16 * LDW + k * 16, LDW);
            wmma::load_matrix_sync(b, sW + k * 16 * LDW + nt * 16, LDW);
            wmma::mma_sync(acc, a, b, acc);
        }
        wmma::store_matrix_sync(sOut[w], acc, 16, wmma::mem_row_major);
        __syncwarp();

        int row0 = blockIdx.x * 32 + rt * 16;
#pragma unroll
        for (int i = lane; i < 64; i += 32) {     // 16 rows x 4 uint2-groups
            int r = i >> 2, c4 = i & 3;
            const float* p = sOut[w] + r * 16 + c4 * 4;
            *(uint2*)(out + (size_t)(row0 + r) * 64 + nt * 16 + c4 * 4) =
                f4_to_h4(p[0], p[1], p[2], p[3]);
        }
    }
}

// ---------------- fused: a = agg(h)+b; pool atomics ----------------
__global__ __launch_bounds__(512)
void k_fused_pool(const __half* __restrict__ h, const float* __restrict__ bias,
                  const int* __restrict__ ba1, const int* __restrict__ ba2) {
    int t = threadIdx.x;
    int node = blockIdx.x * 32 + (t >> 4);
    int lq = t & 15;

    float a0, a1, a2, a3;
    agg_node((const uint2*)h, node, lq, a0, a1, a2, a3);
    float4 b4 = *(const float4*)(bias + lq * 4);
    a0 += b4.x; a1 += b4.y; a2 += b4.z; a3 += b4.w;

    int g = (node < NN) ? ba1[node] : (NG + ba2[node - NN]);
    float* p = g_pool + g * HID + lq * 4;
    atomicAdd(p + 0, a0);
    atomicAdd(p + 1, a1);
    atomicAdd(p + 2, a2);
    atomicAdd(p + 3, a3);
    if (lq == 0) atomicAdd(&g_cnt[g], 1.0f);
}

// ---------------- fused mlp + distance ----------------
__global__ void k_mlp_dist(const float* __restrict__ Wlin, const float* __restrict__ blin,
                           float* __restrict__ out) {
    int g = blockIdx.x;       // 256
    int c = threadIdx.x;      // 64
    __shared__ float p1[64], p2[64], red[64];
    float cn1 = fmaxf(g_cnt[g], 1.0f);
    float cn2 = fmaxf(g_cnt[g + NG], 1.0f);
    p1[c] = g_pool[g * HID + c] / cn1;
    p2[c] = g_pool[(g + NG) * HID + c] / cn2;
    __syncthreads();
    float bv = blin[c];
    float e1 = bv, e2 = bv;
#pragma unroll 8
    for (int k = 0; k < 64; k++) {
        float w = Wlin[k * 64 + c];
        e1 += p1[k] * w;
        e2 += p2[k] * w;
    }
    float d = e1 - e2 + PD_EPS;
    red[c] = d * d;
    __syncthreads();
    if (c < 32) {
        float v = red[c] + red[c + 32];
#pragma unroll
        for (int off = 16; off > 0; off >>= 1)
            v += __shfl_down_sync(0xffffffff, v, off);
        if (c == 0) out[g] = sqrtf(v);
    }
}

// ---------------- host orchestration ----------------
extern "C" void kernel_launch(void* const* d_in, const int* in_sizes, int n_in,
                              void* d_out, int out_size) {
    const float* x1  = (const float*)d_in[0];
    const int*   ei1 = (const int*)d_in[1];
    const int*   ba1 = (const int*)d_in[2];
    const float* x2  = (const float*)d_in[3];
    const int*   ei2 = (const int*)d_in[4];
    const int*   ba2 = (const int*)d_in[5];
    const float* W1  = (const float*)d_in[6];
    const float* b1  = (const float*)d_in[7];
    const float* W2  = (const float*)d_in[8];
    const float* b2  = (const float*)d_in[9];
    const float* W3  = (const float*)d_in[10];
    const float* b3  = (const float*)d_in[11];
    const float* Wl  = (const float*)d_in[12];
    const float* bl  = (const float*)d_in[13];
    float* out = (float*)d_out;

    void *px, *ph0, *ph1, *pw;
    cudaGetSymbolAddress(&px, g_x16);
    cudaGetSymbolAddress(&ph0, g_h0);
    cudaGetSymbolAddress(&ph1, g_h1);
    cudaGetSymbolAddress(&pw, g_wh);
    __half* x16 = (__half*)px;
    __half* h0 = (__half*)ph0;
    __half* h1 = (__half*)ph1;
    __half* wh = (__half*)pw;

    const int* src1 = ei1;          const int* dst1 = ei1 + NE;
    const int* src2 = ei2;          const int* dst2 = ei2 + NE;

    int nbN  = (NN2 + 255) / 256;
    int nbE  = (NE2 + 255) / 256;
    int nbG  = (NN2 + 255) / 256;              // 256 rows/block
    int nbF  = NN2 / 32;                       // 6250
    int nbCX = (NN2 * FIN / 4 + 255) / 256;
    int nbCW = (FIN * HID + 2 * HID * HID + 255) / 256;

    // order chosen so the profiler's captured launch (#3) is the hot GEMM
    k_cvt_w<<<nbCW, 256>>>(W1, W2, W3);                 // 0
    k_cvt_x<<<nbCX, 256>>>(x1, x2);                     // 1
    k_init<<<nbN, 256>>>();                             // 2
    k_gemm_tc<FIN><<<nbG, 256>>>(x16, wh, h0);          // 3  (hot)
    k_deg_count<<<nbE, 256>>>(dst1, dst2);              // 4
    k_scanA<<<SCAN_NB2, 1024>>>();                      // 5
    k_scanC<<<SCAN_NB2, 1024>>>();                      // 6
    k_fill<<<nbE, 256>>>(src1, dst1, src2, dst2);       // 7

    // fused layers
    k_fused<<<nbF, 512>>>(h0, wh + FIN * HID, b1, h1);                    // agg1+relu -> @W2
    k_fused<<<nbF, 512>>>(h1, wh + FIN * HID + HID * HID, b2, h0);        // agg2+relu -> @W3
    k_fused_pool<<<nbF, 512>>>(h0, b3, ba1, ba2);                         // agg3 + pool
    k_mlp_dist<<<NG, 64>>>(Wl, bl, out);
}